// round 2
// baseline (speedup 1.0000x reference)
#include <cuda_runtime.h>
#include <cstdint>

#define BB   4
#define NP   8192
#define SP   2048
#define D1   128
#define D2   256
#define CIN  384
#define COUT 256
#define BN_EPS 1e-5f

// ---------------- scratch (no cudaMalloc allowed) ----------------
// g_xin is dead after the fuse GEMM, so it doubles as the block intermediate "y".
__device__ float g_p2t[BB * SP * D2];      //  8 MB  points2 transposed [b][s][c]
__device__ float g_xin[BB * CIN * NP];     // 50 MB  concat input [b][c][n]; later reused as y
__device__ float g_t  [BB * COUT * NP];    // 33 MB  raw GEMM output
__device__ float g_x  [BB * COUT * NP];    // 33 MB  residual trunk x
__device__ int   g_idx[BB * NP * 3];
__device__ float g_w  [BB * NP * 3];
__device__ float g_na [COUT];
__device__ float g_nb [COUT];

// ---------------- packed f32x2 helpers (sm_100+) ----------------
__device__ __forceinline__ unsigned long long pack2(float a) {
    unsigned long long r;
    asm("mov.b64 %0, {%1, %1};" : "=l"(r) : "f"(a));
    return r;
}
__device__ __forceinline__ void ffma2(unsigned long long& c,
                                      unsigned long long a,
                                      unsigned long long b) {
    asm("fma.rn.f32x2 %0, %1, %2, %0;" : "+l"(c) : "l"(a), "l"(b));
}
__device__ __forceinline__ float2 unpack2(unsigned long long c) {
    float2 f;
    asm("mov.b64 {%0, %1}, %2;" : "=f"(f.x), "=f"(f.y) : "l"(c));
    return f;
}

// ---------------- KNN (3-NN over S=2048, smem-resident) ----------------
__global__ void __launch_bounds__(256) knn_kernel(const float* __restrict__ xyz1,
                                                  const float* __restrict__ xyz2) {
    __shared__ float sx[SP], sy[SP], sz[SP], sn[SP];
    int b = blockIdx.y;
    const float* x2 = xyz2 + (size_t)b * 3 * SP;
    for (int i = threadIdx.x; i < SP; i += 256) {
        float X = x2[i], Y = x2[SP + i], Z = x2[2 * SP + i];
        sx[i] = X; sy[i] = Y; sz[i] = Z; sn[i] = X * X + Y * Y + Z * Z;
    }
    __syncthreads();
    int n = blockIdx.x * 256 + threadIdx.x;
    const float* x1 = xyz1 + (size_t)b * 3 * NP;
    float qx = x1[n], qy = x1[NP + n], qz = x1[2 * NP + n];
    float qn = qx * qx + qy * qy + qz * qz;

    float d0 = 3.4e38f, d1 = 3.4e38f, d2v = 3.4e38f;
    int i0 = 0, i1 = 0, i2 = 0;
#pragma unroll 4
    for (int s = 0; s < SP; s++) {
        float dot = qx * sx[s] + qy * sy[s] + qz * sz[s];
        float d = qn + sn[s] - 2.0f * dot;     // same formula as reference
        if (d < d2v) {
            if (d < d1) {
                d2v = d1; i2 = i1;
                if (d < d0) { d1 = d0; i1 = i0; d0 = d; i0 = s; }
                else        { d1 = d;  i1 = s; }
            } else { d2v = d; i2 = s; }
        }
    }
    float r0 = 1.0f / (d0 + 1e-8f);
    float r1 = 1.0f / (d1 + 1e-8f);
    float r2 = 1.0f / (d2v + 1e-8f);
    float inv = 1.0f / (r0 + r1 + r2);
    size_t base = ((size_t)b * NP + n) * 3;
    g_idx[base] = i0; g_idx[base + 1] = i1; g_idx[base + 2] = i2;
    g_w[base] = r0 * inv; g_w[base + 1] = r1 * inv; g_w[base + 2] = r2 * inv;
}

// ---------------- transpose points2 [b][c][s] -> [b][s][c] ----------------
__global__ void transpose_p2_kernel(const float* __restrict__ p2) {
    __shared__ float tile[32][33];
    int b = blockIdx.z;
    int s0 = blockIdx.x * 32, c0 = blockIdx.y * 32;
    int tx = threadIdx.x, ty = threadIdx.y;  // 32 x 8
    const float* src = p2 + (size_t)b * D2 * SP;
#pragma unroll
    for (int j = 0; j < 32; j += 8)
        tile[ty + j][tx] = src[(size_t)(c0 + ty + j) * SP + s0 + tx];
    __syncthreads();
    float* dst = g_p2t + (size_t)b * SP * D2;
#pragma unroll
    for (int j = 0; j < 32; j += 8)
        dst[(size_t)(s0 + ty + j) * D2 + c0 + tx] = tile[tx][ty + j];
}

// ---------------- interpolation: gather rows of p2t, write xin[128..383][n] ----------------
__global__ void __launch_bounds__(256) interp_kernel() {
    __shared__ float tile[D2][33];
    __shared__ float sw[32][3];
    __shared__ int   si[32][3];
    int b = blockIdx.y;
    int n0 = blockIdx.x * 32;
    int tid = threadIdx.x;
    if (tid < 96) {
        int q = tid / 3, k = tid % 3;
        size_t base = ((size_t)b * NP + n0 + q) * 3 + k;
        sw[q][k] = g_w[base];
        si[q][k] = g_idx[base];
    }
    __syncthreads();
    const float* f2 = g_p2t + (size_t)b * SP * D2;
    int c = tid;  // 0..255
#pragma unroll 4
    for (int q = 0; q < 32; q++) {
        float v = sw[q][0] * f2[(size_t)si[q][0] * D2 + c]
                + sw[q][1] * f2[(size_t)si[q][1] * D2 + c]
                + sw[q][2] * f2[(size_t)si[q][2] * D2 + c];
        tile[c][q] = v;
    }
    __syncthreads();
    float* dst = g_xin + (size_t)b * CIN * NP + (size_t)D1 * NP + n0;
    int q = tid & 31, rr = tid >> 5;
#pragma unroll
    for (int r = 0; r < 32; r++) {
        int cc = r * 8 + rr;
        dst[(size_t)cc * NP + q] = tile[cc][q];
    }
}

// ---------------- copy points1 into xin channels [0..127] ----------------
__global__ void copy_p1_kernel(const float* __restrict__ p1) {
    int i = blockIdx.x * 256 + threadIdx.x;  // over BB*D1*NP/4 float4s
    const int per = D1 * NP / 4;
    int b = i / per, r = i % per;
    const float4* src = (const float4*)p1;
    float4* dst = (float4*)g_xin;
    dst[(size_t)b * (CIN * NP / 4) + r] = src[i];
}

// ---------------- fp32 SIMT GEMM, 128x128x8 tiles, packed-f32x2 FFMA ----------------
// Y[b][m][n] = sum_c A[m][c] * X[b][c][n] + bias[m]
template <int K>
__global__ void __launch_bounds__(256) gemm_kernel(const float* __restrict__ A,
                                                   const float* __restrict__ bias,
                                                   const float* __restrict__ X,
                                                   float* __restrict__ Y) {
    __shared__ float As[2][8][132];
    __shared__ float Bs[2][8][128];

    int tid = threadIdx.x;
    int b = blockIdx.z;
    int n0 = blockIdx.x * 128;
    int m0 = blockIdx.y * 128;
    const float* Xb = X + (size_t)b * K * NP;
    float* Yb = Y + (size_t)b * COUT * NP;

    int ar = tid >> 1;            // A row 0..127
    int ak = (tid & 1) * 4;       // A k offset 0/4
    int bk = tid >> 5;            // B k 0..7
    int bn = (tid & 31) * 4;      // B n offset

    int wid = tid >> 5, lane = tid & 31;
    int wm = wid & 1, wn = wid >> 1;
    int lm = lane & 7, ln = lane >> 3;
    int mBase = wm * 64 + lm * 8;
    int nBase = wn * 32 + ln * 8;

    unsigned long long c2[8][4];
#pragma unroll
    for (int i = 0; i < 8; i++)
#pragma unroll
        for (int j = 0; j < 4; j++) c2[i][j] = 0ull;

    const int NT = K / 8;

    float4 aReg = *(const float4*)&A[(size_t)(m0 + ar) * K + ak];
    float4 bReg = *(const float4*)&Xb[(size_t)bk * NP + n0 + bn];
    As[0][ak + 0][ar] = aReg.x;
    As[0][ak + 1][ar] = aReg.y;
    As[0][ak + 2][ar] = aReg.z;
    As[0][ak + 3][ar] = aReg.w;
    *(float4*)&Bs[0][bk][bn] = bReg;
    __syncthreads();

    int buf = 0;
    for (int t = 0; t < NT; t++) {
        if (t + 1 < NT) {
            aReg = *(const float4*)&A[(size_t)(m0 + ar) * K + (t + 1) * 8 + ak];
            bReg = *(const float4*)&Xb[(size_t)((t + 1) * 8 + bk) * NP + n0 + bn];
        }
#pragma unroll
        for (int k = 0; k < 8; k++) {
            float4 a0 = *(const float4*)&As[buf][k][mBase];
            float4 a1 = *(const float4*)&As[buf][k][mBase + 4];
            ulonglong2 bv0 = *(const ulonglong2*)&Bs[buf][k][nBase];
            ulonglong2 bv1 = *(const ulonglong2*)&Bs[buf][k][nBase + 4];
            unsigned long long b2[4] = {bv0.x, bv0.y, bv1.x, bv1.y};
            unsigned long long a2[8];
            a2[0] = pack2(a0.x); a2[1] = pack2(a0.y);
            a2[2] = pack2(a0.z); a2[3] = pack2(a0.w);
            a2[4] = pack2(a1.x); a2[5] = pack2(a1.y);
            a2[6] = pack2(a1.z); a2[7] = pack2(a1.w);
#pragma unroll
            for (int i = 0; i < 8; i++)
#pragma unroll
                for (int j = 0; j < 4; j++) ffma2(c2[i][j], a2[i], b2[j]);
        }
        if (t + 1 < NT) {
            buf ^= 1;
            As[buf][ak + 0][ar] = aReg.x;
            As[buf][ak + 1][ar] = aReg.y;
            As[buf][ak + 2][ar] = aReg.z;
            As[buf][ak + 3][ar] = aReg.w;
            *(float4*)&Bs[buf][bk][bn] = bReg;
            __syncthreads();
        }
    }

#pragma unroll
    for (int i = 0; i < 8; i++) {
        int m = m0 + mBase + i;
        float bs = bias[m];
        float* out = &Yb[(size_t)m * NP + n0 + nBase];
        float2 f0 = unpack2(c2[i][0]);
        float2 f1 = unpack2(c2[i][1]);
        float2 f2 = unpack2(c2[i][2]);
        float2 f3 = unpack2(c2[i][3]);
        float4 o0 = make_float4(f0.x + bs, f0.y + bs, f1.x + bs, f1.y + bs);
        float4 o1 = make_float4(f2.x + bs, f2.y + bs, f3.x + bs, f3.y + bs);
        *(float4*)&out[0] = o0;
        *(float4*)&out[4] = o1;
    }
}

// ---------------- BN stats: one block per channel, deterministic ----------------
__global__ void __launch_bounds__(256) stats_kernel(const float* __restrict__ T,
                                                    const float* __restrict__ gamma,
                                                    const float* __restrict__ beta) {
    int c = blockIdx.x;
    int tid = threadIdx.x;
    float s = 0.f, s2 = 0.f;
    for (int b = 0; b < BB; b++) {
        const float* row = T + (size_t)b * COUT * NP + (size_t)c * NP;
        for (int n = tid; n < NP; n += 256) {
            float v = row[n];
            s += v;
            s2 += v * v;
        }
    }
    __shared__ float rs[256], rs2[256];
    rs[tid] = s; rs2[tid] = s2;
    __syncthreads();
    for (int o = 128; o > 0; o >>= 1) {
        if (tid < o) { rs[tid] += rs[tid + o]; rs2[tid] += rs2[tid + o]; }
        __syncthreads();
    }
    if (tid == 0) {
        float inv = 1.0f / (float)(BB * NP);
        float mean = rs[0] * inv;
        float var = rs2[0] * inv - mean * mean;
        float a = gamma[c] * rsqrtf(var + BN_EPS);
        g_na[c] = a;
        g_nb[c] = beta[c] - mean * a;
    }
}

// ---------------- elementwise BN-apply kernels ----------------
__global__ void apply_relu_kernel(const float* __restrict__ T, float* __restrict__ O) {
    int i = blockIdx.x * 256 + threadIdx.x;  // float4 index
    int c = (i / (NP / 4)) % COUT;
    float a = g_na[c], bb = g_nb[c];
    float4 v = ((const float4*)T)[i];
    v.x = fmaxf(fmaf(a, v.x, bb), 0.f);
    v.y = fmaxf(fmaf(a, v.y, bb), 0.f);
    v.z = fmaxf(fmaf(a, v.z, bb), 0.f);
    v.w = fmaxf(fmaf(a, v.w, bb), 0.f);
    ((float4*)O)[i] = v;
}

__global__ void apply_res_relu_kernel(const float* __restrict__ T,
                                      const float* __restrict__ Xp,
                                      float* __restrict__ O) {
    int i = blockIdx.x * 256 + threadIdx.x;
    int c = (i / (NP / 4)) % COUT;
    float a = g_na[c], bb = g_nb[c];
    float4 v = ((const float4*)T)[i];
    float4 xp = ((const float4*)Xp)[i];
    v.x = fmaxf(fmaf(a, v.x, bb) + xp.x, 0.f);
    v.y = fmaxf(fmaf(a, v.y, bb) + xp.y, 0.f);
    v.z = fmaxf(fmaf(a, v.z, bb) + xp.z, 0.f);
    v.w = fmaxf(fmaf(a, v.w, bb) + xp.w, 0.f);
    ((float4*)O)[i] = v;
}

// ---------------- launch ----------------
extern "C" void kernel_launch(void* const* d_in, const int* in_sizes, int n_in,
                              void* d_out, int out_size) {
    const float* xyz1    = (const float*)d_in[0];
    const float* xyz2    = (const float*)d_in[1];
    const float* points1 = (const float*)d_in[2];
    const float* points2 = (const float*)d_in[3];
    const float* fuse_W  = (const float*)d_in[4];
    const float* fuse_b  = (const float*)d_in[5];
    const float* fuse_g  = (const float*)d_in[6];
    const float* fuse_be = (const float*)d_in[7];
    const float* blk_W1  = (const float*)d_in[8];
    const float* blk_b1  = (const float*)d_in[9];
    const float* blk_g1  = (const float*)d_in[10];
    const float* blk_be1 = (const float*)d_in[11];
    const float* blk_W2  = (const float*)d_in[12];
    const float* blk_b2  = (const float*)d_in[13];
    const float* blk_g2  = (const float*)d_in[14];
    const float* blk_be2 = (const float*)d_in[15];
    float* out = (float*)d_out;

    void* pv;
    cudaGetSymbolAddress(&pv, g_xin); float* xin = (float*)pv;  // also reused as y
    cudaGetSymbolAddress(&pv, g_t);   float* t   = (float*)pv;
    cudaGetSymbolAddress(&pv, g_x);   float* x   = (float*)pv;
    float* y = xin;  // g_xin is dead after fuse GEMM

    const int EW_GRID = BB * COUT * NP / 4 / 256;  // 8192
    dim3 ggrid(NP / 128, COUT / 128, BB);          // (64, 2, 4)

    transpose_p2_kernel<<<dim3(SP / 32, D2 / 32, BB), dim3(32, 8)>>>(points2);
    knn_kernel<<<dim3(NP / 256, BB), 256>>>(xyz1, xyz2);
    interp_kernel<<<dim3(NP / 32, BB), 256>>>();
    copy_p1_kernel<<<BB * D1 * NP / 4 / 256, 256>>>(points1);

    // fuse: 384 -> 256, BN, relu -> x
    gemm_kernel<CIN><<<ggrid, 256>>>(fuse_W, fuse_b, xin, t);
    stats_kernel<<<COUT, 256>>>(t, fuse_g, fuse_be);
    apply_relu_kernel<<<EW_GRID, 256>>>(t, x);

    for (int i = 0; i < 2; i++) {
        gemm_kernel<COUT><<<ggrid, 256>>>(blk_W1 + (size_t)i * COUT * COUT,
                                          blk_b1 + (size_t)i * COUT, x, t);
        stats_kernel<<<COUT, 256>>>(t, blk_g1 + (size_t)i * COUT, blk_be1 + (size_t)i * COUT);
        apply_relu_kernel<<<EW_GRID, 256>>>(t, y);

        gemm_kernel<COUT><<<ggrid, 256>>>(blk_W2 + (size_t)i * COUT * COUT,
                                          blk_b2 + (size_t)i * COUT, y, t);
        stats_kernel<<<COUT, 256>>>(t, blk_g2 + (size_t)i * COUT, blk_be2 + (size_t)i * COUT);
        float* dst = (i == 1) ? out : x;
        apply_res_relu_kernel<<<EW_GRID, 256>>>(t, x, dst);
    }
}

// round 4
// speedup vs baseline: 1.4716x; 1.4716x over previous
#include <cuda_runtime.h>
#include <cuda_bf16.h>
#include <cstdint>

#define BB   4
#define NP   8192
#define SP   2048
#define D1   128
#define D2   256
#define CIN  384
#define COUT 256
#define RS   384          // row stride (K elems) of transposed bf16 activation buffers
#define BN_EPS 1e-5f

#define BM   128
#define BN   64
#define BKc  32
#define SST  40           // smem row stride in bf16 (80 B = 5*16B, conflict-free frag loads)

// ---------------- scratch (no cudaMalloc allowed) ----------------
__device__ float g_p2t[BB * SP * D2];                    //  8 MB
__device__ float g_t  [(size_t)BB * COUT * NP];          // 33 MB raw GEMM out
__device__ float g_x  [(size_t)BB * COUT * NP];          // 33 MB residual trunk (fp32)
__device__ __nv_bfloat16 g_bth[(size_t)BB * NP * RS];    // 25 MB X^T hi  [b][n][c]
__device__ __nv_bfloat16 g_btl[(size_t)BB * NP * RS];    // 25 MB X^T lo
__device__ __nv_bfloat16 g_wh[COUT * CIN];               // weight hi (per-layer reuse)
__device__ __nv_bfloat16 g_wl[COUT * CIN];
__device__ int   g_idx[BB * NP * 3];
__device__ float g_w  [BB * NP * 3];
__device__ float g_na [COUT];
__device__ float g_nb [COUT];

__device__ __forceinline__ void bf16_split(float v, __nv_bfloat16& hi, __nv_bfloat16& lo) {
    hi = __float2bfloat16(v);
    lo = __float2bfloat16(v - __bfloat162float(hi));
}

// bf16 HMMA m16n8k16, fp32 accumulate (plain PTX ISA, no arch-suffix feature)
__device__ __forceinline__ void mma16816(float* c, const uint32_t* a, const uint32_t* b) {
    asm volatile(
        "mma.sync.aligned.m16n8k16.row.col.f32.bf16.bf16.f32 "
        "{%0,%1,%2,%3}, {%4,%5,%6,%7}, {%8,%9}, {%0,%1,%2,%3};"
        : "+f"(c[0]), "+f"(c[1]), "+f"(c[2]), "+f"(c[3])
        : "r"(a[0]), "r"(a[1]), "r"(a[2]), "r"(a[3]), "r"(b[0]), "r"(b[1]));
}

// ---------------- KNN (3-NN over S=2048, smem-resident) ----------------
__global__ void __launch_bounds__(256) knn_kernel(const float* __restrict__ xyz1,
                                                  const float* __restrict__ xyz2) {
    __shared__ float sx[SP], sy[SP], sz[SP], sn[SP];
    int b = blockIdx.y;
    const float* x2 = xyz2 + (size_t)b * 3 * SP;
    for (int i = threadIdx.x; i < SP; i += 256) {
        float X = x2[i], Y = x2[SP + i], Z = x2[2 * SP + i];
        sx[i] = X; sy[i] = Y; sz[i] = Z; sn[i] = X * X + Y * Y + Z * Z;
    }
    __syncthreads();
    int n = blockIdx.x * 256 + threadIdx.x;
    const float* x1 = xyz1 + (size_t)b * 3 * NP;
    float qx = x1[n], qy = x1[NP + n], qz = x1[2 * NP + n];
    float qn = qx * qx + qy * qy + qz * qz;

    float d0 = 3.4e38f, d1 = 3.4e38f, d2v = 3.4e38f;
    int i0 = 0, i1 = 0, i2 = 0;
#pragma unroll 4
    for (int s = 0; s < SP; s++) {
        float dot = qx * sx[s] + qy * sy[s] + qz * sz[s];
        float d = qn + sn[s] - 2.0f * dot;
        if (d < d2v) {
            if (d < d1) {
                d2v = d1; i2 = i1;
                if (d < d0) { d1 = d0; i1 = i0; d0 = d; i0 = s; }
                else        { d1 = d;  i1 = s; }
            } else { d2v = d; i2 = s; }
        }
    }
    float r0 = 1.0f / (d0 + 1e-8f);
    float r1 = 1.0f / (d1 + 1e-8f);
    float r2 = 1.0f / (d2v + 1e-8f);
    float inv = 1.0f / (r0 + r1 + r2);
    size_t base = ((size_t)b * NP + n) * 3;
    g_idx[base] = i0; g_idx[base + 1] = i1; g_idx[base + 2] = i2;
    g_w[base] = r0 * inv; g_w[base + 1] = r1 * inv; g_w[base + 2] = r2 * inv;
}

// ---------------- transpose points2 [b][c][s] -> [b][s][c] ----------------
__global__ void transpose_p2_kernel(const float* __restrict__ p2) {
    __shared__ float tile[32][33];
    int b = blockIdx.z;
    int s0 = blockIdx.x * 32, c0 = blockIdx.y * 32;
    int tx = threadIdx.x, ty = threadIdx.y;  // 32 x 8
    const float* src = p2 + (size_t)b * D2 * SP;
#pragma unroll
    for (int j = 0; j < 32; j += 8)
        tile[ty + j][tx] = src[(size_t)(c0 + ty + j) * SP + s0 + tx];
    __syncthreads();
    float* dst = g_p2t + (size_t)b * SP * D2;
#pragma unroll
    for (int j = 0; j < 32; j += 8)
        dst[(size_t)(s0 + ty + j) * D2 + c0 + tx] = tile[tx][ty + j];
}

// ---------------- interp: writes bt rows [n][128..383] as bf16 hi/lo ----------------
__global__ void __launch_bounds__(256) interp_kernel() {
    __shared__ float sw[32][3];
    __shared__ int   si[32][3];
    int b = blockIdx.y;
    int n0 = blockIdx.x * 32;
    int tid = threadIdx.x;
    if (tid < 96) {
        int q = tid / 3, k = tid % 3;
        size_t base = ((size_t)b * NP + n0 + q) * 3 + k;
        sw[q][k] = g_w[base];
        si[q][k] = g_idx[base];
    }
    __syncthreads();
    const float* f2 = g_p2t + (size_t)b * SP * D2;
    int c = tid;  // 0..255
#pragma unroll 4
    for (int q = 0; q < 32; q++) {
        float v = sw[q][0] * f2[(size_t)si[q][0] * D2 + c]
                + sw[q][1] * f2[(size_t)si[q][1] * D2 + c]
                + sw[q][2] * f2[(size_t)si[q][2] * D2 + c];
        __nv_bfloat16 hi, lo;
        bf16_split(v, hi, lo);
        size_t o = ((size_t)b * NP + n0 + q) * RS + D1 + c;
        g_bth[o] = hi;
        g_btl[o] = lo;
    }
}

// ---------------- points1 [b][c][n] -> bt rows [n][0..127] bf16 hi/lo ----------------
__global__ void convert_p1_kernel(const float* __restrict__ p1) {
    __shared__ float tile[32][33];
    int b = blockIdx.z;
    int n0 = blockIdx.x * 32, c0 = blockIdx.y * 32;
    int tx = threadIdx.x, ty = threadIdx.y;  // 32 x 8
#pragma unroll
    for (int j = 0; j < 32; j += 8)
        tile[ty + j][tx] = p1[((size_t)b * D1 + c0 + ty + j) * NP + n0 + tx];
    __syncthreads();
#pragma unroll
    for (int j = 0; j < 32; j += 8) {
        float v = tile[tx][ty + j];
        __nv_bfloat16 hi, lo;
        bf16_split(v, hi, lo);
        size_t o = ((size_t)b * NP + n0 + ty + j) * RS + c0 + tx;
        g_bth[o] = hi;
        g_btl[o] = lo;
    }
}

// ---------------- weight fp32 -> bf16 hi/lo ----------------
__global__ void convert_w_kernel(const float* __restrict__ W, int total) {
    int i = blockIdx.x * 256 + threadIdx.x;
    if (i < total) {
        __nv_bfloat16 hi, lo;
        bf16_split(W[i], hi, lo);
        g_wh[i] = hi;
        g_wl[i] = lo;
    }
}

// ---------------- mma.sync GEMM: t[b][m][n] = sum_c W[m][c]*X[b][c][n] + bias[m]
// A = W K-major (hi/lo), B = X^T rows K-major (hi/lo), 3-product bf16 split.
// CTA: 128(M) x 64(N), BK=32, double-buffered smem, 8 warps as 4(M) x 2(N).
template <int K>
__global__ void __launch_bounds__(256) gemm_mma_kernel(const float* __restrict__ bias) {
    extern __shared__ __nv_bfloat16 sm[];
    const int ASZ = BM * SST;            // 5120 bf16
    const int BSZ = BN * SST;            // 2560 bf16
    const int STG = 2 * ASZ + 2 * BSZ;   // 15360 bf16 = 30720 B per stage

    int tid = threadIdx.x, lane = tid & 31, wid = tid >> 5;
    int wm = wid & 3, wn = wid >> 2;     // 4 x 2 warp grid
    int b = blockIdx.z;
    int n0 = blockIdx.x * BN, m0 = blockIdx.y * BM;

    int r  = lane >> 2;          // 0..7
    int kq = (lane & 3) * 2;     // 0,2,4,6

    // global->smem load mapping
    int a_row = tid >> 1;                 // with i*? -> see below: 512 uint4 per A matrix
    (void)a_row;

    float acc[2][4][4];
#pragma unroll
    for (int i = 0; i < 2; i++)
#pragma unroll
        for (int j = 0; j < 4; j++)
#pragma unroll
            for (int q = 0; q < 4; q++) acc[i][j][q] = 0.f;

    const int NT = K / BKc;

    const __nv_bfloat16* bth_b = g_bth + (size_t)b * NP * RS;
    const __nv_bfloat16* btl_b = g_btl + (size_t)b * NP * RS;

    // prefetch stage 0
    uint4 pah[2], pal[2], pbh, pbl;
    {
        int kc = 0;
#pragma unroll
        for (int i = 0; i < 2; i++) {
            int idx = tid + i * 256;             // 0..511
            int row = idx >> 2, c = idx & 3;     // c in 16B units
            pah[i] = *(const uint4*)(g_wh + (size_t)(m0 + row) * K + kc + c * 8);
            pal[i] = *(const uint4*)(g_wl + (size_t)(m0 + row) * K + kc + c * 8);
        }
        int row = tid >> 2, c = tid & 3;
        pbh = *(const uint4*)(bth_b + (size_t)(n0 + row) * RS + kc + c * 8);
        pbl = *(const uint4*)(btl_b + (size_t)(n0 + row) * RS + kc + c * 8);
    }
    {
        __nv_bfloat16* st = sm;
#pragma unroll
        for (int i = 0; i < 2; i++) {
            int idx = tid + i * 256;
            int row = idx >> 2, c = idx & 3;
            *(uint4*)(st + row * SST + c * 8)       = pah[i];
            *(uint4*)(st + ASZ + row * SST + c * 8) = pal[i];
        }
        int row = tid >> 2, c = tid & 3;
        *(uint4*)(st + 2 * ASZ + row * SST + c * 8)       = pbh;
        *(uint4*)(st + 2 * ASZ + BSZ + row * SST + c * 8) = pbl;
    }
    __syncthreads();

    for (int t = 0; t < NT; t++) {
        if (t + 1 < NT) {
            int kc = (t + 1) * BKc;
#pragma unroll
            for (int i = 0; i < 2; i++) {
                int idx = tid + i * 256;
                int row = idx >> 2, c = idx & 3;
                pah[i] = *(const uint4*)(g_wh + (size_t)(m0 + row) * K + kc + c * 8);
                pal[i] = *(const uint4*)(g_wl + (size_t)(m0 + row) * K + kc + c * 8);
            }
            int row = tid >> 2, c = tid & 3;
            pbh = *(const uint4*)(bth_b + (size_t)(n0 + row) * RS + kc + c * 8);
            pbl = *(const uint4*)(btl_b + (size_t)(n0 + row) * RS + kc + c * 8);
        }

        __nv_bfloat16* st = sm + (t & 1) * STG;
        const __nv_bfloat16* Ah_s = st;
        const __nv_bfloat16* Al_s = st + ASZ;
        const __nv_bfloat16* Bh_s = st + 2 * ASZ;
        const __nv_bfloat16* Bl_s = st + 2 * ASZ + BSZ;

#pragma unroll
        for (int k16 = 0; k16 < BKc; k16 += 16) {
            uint32_t ah[2][4], al[2][4], bh[4][2], bl[4][2];
#pragma unroll
            for (int i = 0; i < 2; i++) {
                int row = wm * 32 + i * 16 + r;
                ah[i][0] = *(const uint32_t*)(Ah_s + row * SST + k16 + kq);
                ah[i][1] = *(const uint32_t*)(Ah_s + (row + 8) * SST + k16 + kq);
                ah[i][2] = *(const uint32_t*)(Ah_s + row * SST + k16 + kq + 8);
                ah[i][3] = *(const uint32_t*)(Ah_s + (row + 8) * SST + k16 + kq + 8);
                al[i][0] = *(const uint32_t*)(Al_s + row * SST + k16 + kq);
                al[i][1] = *(const uint32_t*)(Al_s + (row + 8) * SST + k16 + kq);
                al[i][2] = *(const uint32_t*)(Al_s + row * SST + k16 + kq + 8);
                al[i][3] = *(const uint32_t*)(Al_s + (row + 8) * SST + k16 + kq + 8);
            }
#pragma unroll
            for (int j = 0; j < 4; j++) {
                int n = wn * 32 + j * 8 + r;
                bh[j][0] = *(const uint32_t*)(Bh_s + n * SST + k16 + kq);
                bh[j][1] = *(const uint32_t*)(Bh_s + n * SST + k16 + kq + 8);
                bl[j][0] = *(const uint32_t*)(Bl_s + n * SST + k16 + kq);
                bl[j][1] = *(const uint32_t*)(Bl_s + n * SST + k16 + kq + 8);
            }
#pragma unroll
            for (int i = 0; i < 2; i++)
#pragma unroll
                for (int j = 0; j < 4; j++) {
                    mma16816(acc[i][j], ah[i], bh[j]);
                    mma16816(acc[i][j], ah[i], bl[j]);
                    mma16816(acc[i][j], al[i], bh[j]);
                }
        }

        if (t + 1 < NT) {
            __nv_bfloat16* sn_ = sm + ((t + 1) & 1) * STG;
            __syncthreads();
#pragma unroll
            for (int i = 0; i < 2; i++) {
                int idx = tid + i * 256;
                int row = idx >> 2, c = idx & 3;
                *(uint4*)(sn_ + row * SST + c * 8)       = pah[i];
                *(uint4*)(sn_ + ASZ + row * SST + c * 8) = pal[i];
            }
            int row = tid >> 2, c = tid & 3;
            *(uint4*)(sn_ + 2 * ASZ + row * SST + c * 8)       = pbh;
            *(uint4*)(sn_ + 2 * ASZ + BSZ + row * SST + c * 8) = pbl;
            __syncthreads();
        }
    }

    // epilogue: add bias, write fp32 g_t
    float* Yb = g_t + (size_t)b * COUT * NP;
#pragma unroll
    for (int i = 0; i < 2; i++) {
        int m = m0 + wm * 32 + i * 16 + r;
        float bs0 = bias[m], bs8 = bias[m + 8];
#pragma unroll
        for (int j = 0; j < 4; j++) {
            int n = n0 + wn * 32 + j * 8 + kq;
            float2 v0 = make_float2(acc[i][j][0] + bs0, acc[i][j][1] + bs0);
            float2 v1 = make_float2(acc[i][j][2] + bs8, acc[i][j][3] + bs8);
            *(float2*)(Yb + (size_t)m * NP + n)       = v0;
            *(float2*)(Yb + (size_t)(m + 8) * NP + n) = v1;
        }
    }
}

// ---------------- BN stats: one block per channel, deterministic ----------------
__global__ void __launch_bounds__(256) stats_kernel(const float* __restrict__ gamma,
                                                    const float* __restrict__ beta) {
    int c = blockIdx.x;
    int tid = threadIdx.x;
    float s = 0.f, s2 = 0.f;
    for (int b = 0; b < BB; b++) {
        const float* row = g_t + ((size_t)b * COUT + c) * NP;
        for (int n = tid; n < NP; n += 256) {
            float v = row[n];
            s += v; s2 += v * v;
        }
    }
    __shared__ float rs[256], rs2[256];
    rs[tid] = s; rs2[tid] = s2;
    __syncthreads();
    for (int o = 128; o > 0; o >>= 1) {
        if (tid < o) { rs[tid] += rs[tid + o]; rs2[tid] += rs2[tid + o]; }
        __syncthreads();
    }
    if (tid == 0) {
        float inv = 1.0f / (float)(BB * NP);
        float mean = rs[0] * inv;
        float var = rs2[0] * inv - mean * mean;
        float a = gamma[c] * rsqrtf(var + BN_EPS);
        g_na[c] = a;
        g_nb[c] = beta[c] - mean * a;
    }
}

// ---------------- fused BN-apply (+residual) (+fp32 out) (+transposed bf16 out) ----------------
template <bool RES, bool WF32, bool WBT>
__global__ void applyT_kernel(const float* __restrict__ Xp, float* __restrict__ O) {
    __shared__ float ts[32][33];
    int b = blockIdx.z;
    int n0 = blockIdx.x * 32, c0 = blockIdx.y * 32;
    int tx = threadIdx.x, ty = threadIdx.y;  // 32 x 8
#pragma unroll
    for (int j = 0; j < 32; j += 8) {
        int c = c0 + ty + j;
        size_t off = ((size_t)b * COUT + c) * NP + n0 + tx;
        float u = fmaf(g_na[c], g_t[off], g_nb[c]);
        if (RES) u += Xp[off];
        u = fmaxf(u, 0.f);
        if (WF32) O[off] = u;
        ts[ty + j][tx] = u;
    }
    if (WBT) {
        __syncthreads();
#pragma unroll
        for (int j = 0; j < 32; j += 8) {
            float v = ts[tx][ty + j];
            __nv_bfloat16 hi, lo;
            bf16_split(v, hi, lo);
            size_t o = ((size_t)b * NP + n0 + ty + j) * RS + c0 + tx;
            g_bth[o] = hi;
            g_btl[o] = lo;
        }
    }
}

// ---------------- launch ----------------
extern "C" void kernel_launch(void* const* d_in, const int* in_sizes, int n_in,
                              void* d_out, int out_size) {
    const float* xyz1    = (const float*)d_in[0];
    const float* xyz2    = (const float*)d_in[1];
    const float* points1 = (const float*)d_in[2];
    const float* points2 = (const float*)d_in[3];
    const float* fuse_W  = (const float*)d_in[4];
    const float* fuse_b  = (const float*)d_in[5];
    const float* fuse_g  = (const float*)d_in[6];
    const float* fuse_be = (const float*)d_in[7];
    const float* blk_W1  = (const float*)d_in[8];
    const float* blk_b1  = (const float*)d_in[9];
    const float* blk_g1  = (const float*)d_in[10];
    const float* blk_be1 = (const float*)d_in[11];
    const float* blk_W2  = (const float*)d_in[12];
    const float* blk_b2  = (const float*)d_in[13];
    const float* blk_g2  = (const float*)d_in[14];
    const float* blk_be2 = (const float*)d_in[15];
    float* out = (float*)d_out;

    void* pv;
    cudaGetSymbolAddress(&pv, g_x); float* x = (float*)pv;

    const int SMEM_GEMM = 2 * (2 * BM * SST + 2 * BN * SST) * 2;  // 61440 B
    cudaFuncSetAttribute(gemm_mma_kernel<CIN>,  cudaFuncAttributeMaxDynamicSharedMemorySize, SMEM_GEMM);
    cudaFuncSetAttribute(gemm_mma_kernel<COUT>, cudaFuncAttributeMaxDynamicSharedMemorySize, SMEM_GEMM);

    dim3 ggrid(NP / BN, COUT / BM, BB);                 // (128, 2, 4)
    dim3 agrid(NP / 32, COUT / 32, BB);                 // (256, 8, 4)
    dim3 ablk(32, 8);

    transpose_p2_kernel<<<dim3(SP / 32, D2 / 32, BB), dim3(32, 8)>>>(points2);
    knn_kernel<<<dim3(NP / 256, BB), 256>>>(xyz1, xyz2);
    interp_kernel<<<dim3(NP / 32, BB), 256>>>();
    convert_p1_kernel<<<dim3(NP / 32, D1 / 32, BB), ablk>>>(points1);

    // fuse: 384 -> 256, BN, relu -> x (fp32) + bt (bf16 T)
    convert_w_kernel<<<(COUT * CIN + 255) / 256, 256>>>(fuse_W, COUT * CIN);
    gemm_mma_kernel<CIN><<<ggrid, 256, SMEM_GEMM>>>(fuse_b);
    stats_kernel<<<COUT, 256>>>(fuse_g, fuse_be);
    applyT_kernel<false, true, true><<<agrid, ablk>>>(nullptr, x);

    for (int i = 0; i < 2; i++) {
        convert_w_kernel<<<(COUT * COUT + 255) / 256, 256>>>(blk_W1 + (size_t)i * COUT * COUT, COUT * COUT);
        gemm_mma_kernel<COUT><<<ggrid, 256, SMEM_GEMM>>>(blk_b1 + (size_t)i * COUT);
        stats_kernel<<<COUT, 256>>>(blk_g1 + (size_t)i * COUT, blk_be1 + (size_t)i * COUT);
        applyT_kernel<false, false, true><<<agrid, ablk>>>(nullptr, nullptr);   // y: bt only

        convert_w_kernel<<<(COUT * COUT + 255) / 256, 256>>>(blk_W2 + (size_t)i * COUT * COUT, COUT * COUT);
        gemm_mma_kernel<COUT><<<ggrid, 256, SMEM_GEMM>>>(blk_b2 + (size_t)i * COUT);
        stats_kernel<<<COUT, 256>>>(blk_g2 + (size_t)i * COUT, blk_be2 + (size_t)i * COUT);
        if (i == 0)
            applyT_kernel<true, true, true><<<agrid, ablk>>>(x, x);
        else
            applyT_kernel<true, true, false><<<agrid, ablk>>>(x, out);
    }
}

// round 5
// speedup vs baseline: 1.6933x; 1.1506x over previous
#include <cuda_runtime.h>
#include <cuda_bf16.h>
#include <cstdint>

#define BB   4
#define NP   8192
#define SP   2048
#define D1   128
#define D2   256
#define CIN  384
#define COUT 256
#define RS   384          // row stride (K elems) of transposed bf16 activation buffers
#define BN_EPS 1e-5f

#define BM   128
#define BN   64
#define BKc  32
#define SST  40           // smem row stride in bf16 (80 B, conflict-free for ldmatrix)
#define NSLOT 512         // (NP/BN) * BB partial-stat slots per channel

// ---------------- scratch (no cudaMalloc allowed) ----------------
__device__ float g_p2t[BB * SP * D2];                    //  8 MB
__device__ float g_t  [(size_t)BB * COUT * NP];          // 33 MB raw GEMM out
__device__ float g_x  [(size_t)BB * COUT * NP];          // 33 MB residual trunk (fp32)
__device__ __nv_bfloat16 g_bth[(size_t)BB * NP * RS];    // 25 MB X^T hi  [b][n][c]
__device__ __nv_bfloat16 g_btl[(size_t)BB * NP * RS];    // 25 MB X^T lo
__device__ __nv_bfloat16 g_wh[COUT * CIN];
__device__ __nv_bfloat16 g_wl[COUT * CIN];
__device__ float g_psum[COUT * NSLOT];                   // per-CTA channel partial sums
__device__ float g_psq [COUT * NSLOT];
__device__ int   g_idx[BB * NP * 3];
__device__ float g_w  [BB * NP * 3];
__device__ float g_na [COUT];
__device__ float g_nb [COUT];

__device__ __forceinline__ void bf16_split(float v, __nv_bfloat16& hi, __nv_bfloat16& lo) {
    hi = __float2bfloat16(v);
    lo = __float2bfloat16(v - __bfloat162float(hi));
}
__device__ __forceinline__ uint32_t smem_u32(const void* p) {
    uint32_t a;
    asm("{ .reg .u64 t; cvta.to.shared.u64 t, %1; cvt.u32.u64 %0, t; }" : "=r"(a) : "l"(p));
    return a;
}
__device__ __forceinline__ void mma16816(float* c, const uint32_t* a, const uint32_t* b) {
    asm volatile(
        "mma.sync.aligned.m16n8k16.row.col.f32.bf16.bf16.f32 "
        "{%0,%1,%2,%3}, {%4,%5,%6,%7}, {%8,%9}, {%0,%1,%2,%3};"
        : "+f"(c[0]), "+f"(c[1]), "+f"(c[2]), "+f"(c[3])
        : "r"(a[0]), "r"(a[1]), "r"(a[2]), "r"(a[3]), "r"(b[0]), "r"(b[1]));
}
__device__ __forceinline__ void ldsm4(uint32_t* r, uint32_t addr) {
    asm volatile("ldmatrix.sync.aligned.m8n8.x4.shared.b16 {%0,%1,%2,%3}, [%4];"
        : "=r"(r[0]), "=r"(r[1]), "=r"(r[2]), "=r"(r[3]) : "r"(addr));
}
__device__ __forceinline__ void cp16(uint32_t daddr, const void* src) {
    asm volatile("cp.async.cg.shared.global [%0], [%1], 16;" :: "r"(daddr), "l"(src));
}

// ---------------- KNN (3-NN over S=2048, smem-resident) ----------------
__global__ void __launch_bounds__(256) knn_kernel(const float* __restrict__ xyz1,
                                                  const float* __restrict__ xyz2) {
    __shared__ float sx[SP], sy[SP], sz[SP], sn[SP];
    int b = blockIdx.y;
    const float* x2 = xyz2 + (size_t)b * 3 * SP;
    for (int i = threadIdx.x; i < SP; i += 256) {
        float X = x2[i], Y = x2[SP + i], Z = x2[2 * SP + i];
        sx[i] = X; sy[i] = Y; sz[i] = Z; sn[i] = X * X + Y * Y + Z * Z;
    }
    __syncthreads();
    int n = blockIdx.x * 256 + threadIdx.x;
    const float* x1 = xyz1 + (size_t)b * 3 * NP;
    float qx = x1[n], qy = x1[NP + n], qz = x1[2 * NP + n];
    float qn = qx * qx + qy * qy + qz * qz;

    float d0 = 3.4e38f, d1 = 3.4e38f, d2v = 3.4e38f;
    int i0 = 0, i1 = 0, i2 = 0;
#pragma unroll 4
    for (int s = 0; s < SP; s++) {
        float dot = qx * sx[s] + qy * sy[s] + qz * sz[s];
        float d = qn + sn[s] - 2.0f * dot;
        if (d < d2v) {
            if (d < d1) {
                d2v = d1; i2 = i1;
                if (d < d0) { d1 = d0; i1 = i0; d0 = d; i0 = s; }
                else        { d1 = d;  i1 = s; }
            } else { d2v = d; i2 = s; }
        }
    }
    float r0 = 1.0f / (d0 + 1e-8f);
    float r1 = 1.0f / (d1 + 1e-8f);
    float r2 = 1.0f / (d2v + 1e-8f);
    float inv = 1.0f / (r0 + r1 + r2);
    size_t base = ((size_t)b * NP + n) * 3;
    g_idx[base] = i0; g_idx[base + 1] = i1; g_idx[base + 2] = i2;
    g_w[base] = r0 * inv; g_w[base + 1] = r1 * inv; g_w[base + 2] = r2 * inv;
}

// ---------------- transpose points2 [b][c][s] -> [b][s][c] ----------------
__global__ void transpose_p2_kernel(const float* __restrict__ p2) {
    __shared__ float tile[32][33];
    int b = blockIdx.z;
    int s0 = blockIdx.x * 32, c0 = blockIdx.y * 32;
    int tx = threadIdx.x, ty = threadIdx.y;  // 32 x 8
#pragma unroll
    for (int j = 0; j < 32; j += 8)
        tile[ty + j][tx] = p2[((size_t)b * D2 + c0 + ty + j) * SP + s0 + tx];
    __syncthreads();
    float* dst = g_p2t + (size_t)b * SP * D2;
#pragma unroll
    for (int j = 0; j < 32; j += 8)
        dst[(size_t)(s0 + ty + j) * D2 + c0 + tx] = tile[tx][ty + j];
}

// ---------------- interp: writes bt rows [n][128..383] as bf16 hi/lo ----------------
__global__ void __launch_bounds__(256) interp_kernel() {
    __shared__ float sw[32][3];
    __shared__ int   si[32][3];
    int b = blockIdx.y;
    int n0 = blockIdx.x * 32;
    int tid = threadIdx.x;
    if (tid < 96) {
        int q = tid / 3, k = tid % 3;
        size_t base = ((size_t)b * NP + n0 + q) * 3 + k;
        sw[q][k] = g_w[base];
        si[q][k] = g_idx[base];
    }
    __syncthreads();
    const float* f2 = g_p2t + (size_t)b * SP * D2;
    int c = tid;  // 0..255
#pragma unroll 4
    for (int q = 0; q < 32; q++) {
        float v = sw[q][0] * f2[(size_t)si[q][0] * D2 + c]
                + sw[q][1] * f2[(size_t)si[q][1] * D2 + c]
                + sw[q][2] * f2[(size_t)si[q][2] * D2 + c];
        __nv_bfloat16 hi, lo;
        bf16_split(v, hi, lo);
        size_t o = ((size_t)b * NP + n0 + q) * RS + D1 + c;
        g_bth[o] = hi;
        g_btl[o] = lo;
    }
}

// ---------------- points1 [b][c][n] -> bt rows [n][0..127] bf16 hi/lo ----------------
__global__ void convert_p1_kernel(const float* __restrict__ p1) {
    __shared__ float tile[32][33];
    int b = blockIdx.z;
    int n0 = blockIdx.x * 32, c0 = blockIdx.y * 32;
    int tx = threadIdx.x, ty = threadIdx.y;  // 32 x 8
#pragma unroll
    for (int j = 0; j < 32; j += 8)
        tile[ty + j][tx] = p1[((size_t)b * D1 + c0 + ty + j) * NP + n0 + tx];
    __syncthreads();
#pragma unroll
    for (int j = 0; j < 32; j += 8) {
        float v = tile[tx][ty + j];
        __nv_bfloat16 hi, lo;
        bf16_split(v, hi, lo);
        size_t o = ((size_t)b * NP + n0 + ty + j) * RS + c0 + tx;
        g_bth[o] = hi;
        g_btl[o] = lo;
    }
}

// ---------------- weight fp32 -> bf16 hi/lo ----------------
__global__ void convert_w_kernel(const float* __restrict__ W, int total) {
    int i = blockIdx.x * 256 + threadIdx.x;
    if (i < total) {
        __nv_bfloat16 hi, lo;
        bf16_split(W[i], hi, lo);
        g_wh[i] = hi;
        g_wl[i] = lo;
    }
}

// ---------------- mma.sync GEMM with ldmatrix + cp.async + fused partial BN stats --
// t[b][m][n] = sum_c W[m][c] * X[b][c][n] + bias[m];  also writes per-CTA
// per-channel partial sum/sumsq into fixed slots (deterministic).
template <int K>
__global__ void __launch_bounds__(256) gemm_mma_kernel(const float* __restrict__ bias) {
    extern __shared__ __nv_bfloat16 sm[];
    const int ASZ = BM * SST;                 // bf16 elems
    const int BSZ = BN * SST;
    const uint32_t ASZB = ASZ * 2, BSZB = BSZ * 2;
    const uint32_t STGB = 2 * ASZB + 2 * BSZB;  // 30720 B per stage

    int tid = threadIdx.x, lane = tid & 31, wid = tid >> 5;
    int wm = wid & 3, wn = wid >> 2;          // 4 x 2 warp grid
    int b = blockIdx.z;
    int n0 = blockIdx.x * BN, m0 = blockIdx.y * BM;
    int r = lane >> 2, qk = lane & 3;

    uint32_t sbase = smem_u32(sm);

    // ldmatrix per-lane address offsets within a stage (bytes, excluding k16)
    int g8 = lane >> 3, lr = lane & 7;
    uint32_t aoff[2], boff[2];
#pragma unroll
    for (int i = 0; i < 2; i++)
        aoff[i] = ((wm * 32 + i * 16 + (g8 & 1) * 8 + lr) * SST + (g8 >> 1) * 8) * 2;
#pragma unroll
    for (int p = 0; p < 2; p++)
        boff[p] = ((wn * 32 + p * 16 + (g8 >> 1) * 8 + lr) * SST + (g8 & 1) * 8) * 2;

    const __nv_bfloat16* bth_b = g_bth + (size_t)b * NP * RS;
    const __nv_bfloat16* btl_b = g_btl + (size_t)b * NP * RS;
    int brow = tid >> 2, bc = tid & 3;

    float acc[2][4][4];
#pragma unroll
    for (int i = 0; i < 2; i++)
#pragma unroll
        for (int j = 0; j < 4; j++)
#pragma unroll
            for (int q = 0; q < 4; q++) acc[i][j][q] = 0.f;

    const int NT = K / BKc;

    auto issue = [&](int t) {
        int kc = t * BKc;
        uint32_t st = sbase + (uint32_t)(t & 1) * STGB;
#pragma unroll
        for (int i = 0; i < 2; i++) {
            int idx = tid + i * 256;
            int row = idx >> 2, c = idx & 3;
            uint32_t d = st + (uint32_t)(row * SST + c * 8) * 2;
            cp16(d, g_wh + (size_t)(m0 + row) * K + kc + c * 8);
            cp16(d + ASZB, g_wl + (size_t)(m0 + row) * K + kc + c * 8);
        }
        {
            uint32_t d = st + 2 * ASZB + (uint32_t)(brow * SST + bc * 8) * 2;
            cp16(d, bth_b + (size_t)(n0 + brow) * RS + kc + bc * 8);
            cp16(d + BSZB, btl_b + (size_t)(n0 + brow) * RS + kc + bc * 8);
        }
        asm volatile("cp.async.commit_group;" ::: "memory");
    };

    issue(0);
    for (int t = 0; t < NT; t++) {
        if (t + 1 < NT) {
            issue(t + 1);
            asm volatile("cp.async.wait_group 1;" ::: "memory");
        } else {
            asm volatile("cp.async.wait_group 0;" ::: "memory");
        }
        __syncthreads();
        uint32_t st = sbase + (uint32_t)(t & 1) * STGB;
#pragma unroll
        for (int k16 = 0; k16 < BKc; k16 += 16) {
            uint32_t kb = (uint32_t)k16 * 2;
            uint32_t ah[2][4], al[2][4], bh[2][4], bl[2][4];
            ldsm4(ah[0], st + aoff[0] + kb);
            ldsm4(ah[1], st + aoff[1] + kb);
            ldsm4(al[0], st + ASZB + aoff[0] + kb);
            ldsm4(al[1], st + ASZB + aoff[1] + kb);
            ldsm4(bh[0], st + 2 * ASZB + boff[0] + kb);
            ldsm4(bh[1], st + 2 * ASZB + boff[1] + kb);
            ldsm4(bl[0], st + 2 * ASZB + BSZB + boff[0] + kb);
            ldsm4(bl[1], st + 2 * ASZB + BSZB + boff[1] + kb);
#pragma unroll
            for (int i = 0; i < 2; i++)
#pragma unroll
                for (int j = 0; j < 4; j++) {
                    const uint32_t* bhj = &bh[j >> 1][(j & 1) * 2];
                    const uint32_t* blj = &bl[j >> 1][(j & 1) * 2];
                    mma16816(acc[i][j], ah[i], bhj);
                    mma16816(acc[i][j], ah[i], blj);
                    mma16816(acc[i][j], al[i], bhj);
                }
        }
        __syncthreads();
    }

    // ---- epilogue: bias add, store fp32, accumulate per-channel partial stats ----
    float* Yb = g_t + (size_t)b * COUT * NP;
    float ssum[4] = {0.f, 0.f, 0.f, 0.f}, ssq[4] = {0.f, 0.f, 0.f, 0.f};
#pragma unroll
    for (int i = 0; i < 2; i++) {
        int m = m0 + wm * 32 + i * 16 + r;
        float bs0 = bias[m], bs8 = bias[m + 8];
#pragma unroll
        for (int j = 0; j < 4; j++) {
            int n = n0 + wn * 32 + j * 8 + qk * 2;
            float v0 = acc[i][j][0] + bs0, v1 = acc[i][j][1] + bs0;
            float v2 = acc[i][j][2] + bs8, v3 = acc[i][j][3] + bs8;
            *(float2*)(Yb + (size_t)m * NP + n)       = make_float2(v0, v1);
            *(float2*)(Yb + (size_t)(m + 8) * NP + n) = make_float2(v2, v3);
            ssum[i * 2]     += v0 + v1;  ssq[i * 2]     += v0 * v0 + v1 * v1;
            ssum[i * 2 + 1] += v2 + v3;  ssq[i * 2 + 1] += v2 * v2 + v3 * v3;
        }
    }
#pragma unroll
    for (int o = 1; o < 4; o <<= 1) {
#pragma unroll
        for (int k = 0; k < 4; k++) {
            ssum[k] += __shfl_xor_sync(0xffffffff, ssum[k], o);
            ssq[k]  += __shfl_xor_sync(0xffffffff, ssq[k], o);
        }
    }
    float* sb = (float*)sm;       // [2][128][2] floats
    __syncthreads();
    if (qk == 0) {
#pragma unroll
        for (int k = 0; k < 4; k++) {
            int row = wm * 32 + (k >> 1) * 16 + (k & 1) * 8 + r;
            sb[(wn * 128 + row) * 2]     = ssum[k];
            sb[(wn * 128 + row) * 2 + 1] = ssq[k];
        }
    }
    __syncthreads();
    if (tid < 128) {
        float S = sb[tid * 2]     + sb[(128 + tid) * 2];
        float Q = sb[tid * 2 + 1] + sb[(128 + tid) * 2 + 1];
        int slot = blockIdx.x + gridDim.x * blockIdx.z;   // 0..511, fixed per CTA
        g_psum[(size_t)(m0 + tid) * NSLOT + slot] = S;
        g_psq [(size_t)(m0 + tid) * NSLOT + slot] = Q;
    }
}

// ---------------- finalize BN: reduce 512 partials per channel (deterministic) ----
__global__ void __launch_bounds__(256) finalize_kernel(const float* __restrict__ gamma,
                                                       const float* __restrict__ beta) {
    int c = blockIdx.x, tid = threadIdx.x;
    float s = g_psum[(size_t)c * NSLOT + tid] + g_psum[(size_t)c * NSLOT + 256 + tid];
    float q = g_psq [(size_t)c * NSLOT + tid] + g_psq [(size_t)c * NSLOT + 256 + tid];
    __shared__ float rs[256], rq[256];
    rs[tid] = s; rq[tid] = q;
    __syncthreads();
    for (int o = 128; o > 0; o >>= 1) {
        if (tid < o) { rs[tid] += rs[tid + o]; rq[tid] += rq[tid + o]; }
        __syncthreads();
    }
    if (tid == 0) {
        float inv = 1.0f / (float)(BB * NP);
        float mean = rs[0] * inv;
        float var = rq[0] * inv - mean * mean;
        float a = gamma[c] * rsqrtf(var + BN_EPS);
        g_na[c] = a;
        g_nb[c] = beta[c] - mean * a;
    }
}

// ---------------- fused BN-apply (+residual) (+fp32 out) (+transposed bf16 out) ----
template <bool RES, bool WF32, bool WBT>
__global__ void applyT_kernel(const float* __restrict__ Xp, float* __restrict__ O) {
    __shared__ float ts[32][33];
    int b = blockIdx.z;
    int n0 = blockIdx.x * 32, c0 = blockIdx.y * 32;
    int tx = threadIdx.x, ty = threadIdx.y;  // 32 x 8
#pragma unroll
    for (int j = 0; j < 32; j += 8) {
        int c = c0 + ty + j;
        size_t off = ((size_t)b * COUT + c) * NP + n0 + tx;
        float u = fmaf(g_na[c], g_t[off], g_nb[c]);
        if (RES) u += Xp[off];
        u = fmaxf(u, 0.f);
        if (WF32) O[off] = u;
        ts[ty + j][tx] = u;
    }
    if (WBT) {
        __syncthreads();
#pragma unroll
        for (int j = 0; j < 32; j += 8) {
            float v = ts[tx][ty + j];
            __nv_bfloat16 hi, lo;
            bf16_split(v, hi, lo);
            size_t o = ((size_t)b * NP + n0 + ty + j) * RS + c0 + tx;
            g_bth[o] = hi;
            g_btl[o] = lo;
        }
    }
}

// ---------------- launch ----------------
extern "C" void kernel_launch(void* const* d_in, const int* in_sizes, int n_in,
                              void* d_out, int out_size) {
    const float* xyz1    = (const float*)d_in[0];
    const float* xyz2    = (const float*)d_in[1];
    const float* points1 = (const float*)d_in[2];
    const float* points2 = (const float*)d_in[3];
    const float* fuse_W  = (const float*)d_in[4];
    const float* fuse_b  = (const float*)d_in[5];
    const float* fuse_g  = (const float*)d_in[6];
    const float* fuse_be = (const float*)d_in[7];
    const float* blk_W1  = (const float*)d_in[8];
    const float* blk_b1  = (const float*)d_in[9];
    const float* blk_g1  = (const float*)d_in[10];
    const float* blk_be1 = (const float*)d_in[11];
    const float* blk_W2  = (const float*)d_in[12];
    const float* blk_b2  = (const float*)d_in[13];
    const float* blk_g2  = (const float*)d_in[14];
    const float* blk_be2 = (const float*)d_in[15];
    float* out = (float*)d_out;

    void* pv;
    cudaGetSymbolAddress(&pv, g_x); float* x = (float*)pv;

    const int SMEM_GEMM = 2 * (2 * BM * SST + 2 * BN * SST) * 2;  // 61440 B
    cudaFuncSetAttribute(gemm_mma_kernel<CIN>,  cudaFuncAttributeMaxDynamicSharedMemorySize, SMEM_GEMM);
    cudaFuncSetAttribute(gemm_mma_kernel<COUT>, cudaFuncAttributeMaxDynamicSharedMemorySize, SMEM_GEMM);

    dim3 ggrid(NP / BN, COUT / BM, BB);                 // (128, 2, 4)
    dim3 agrid(NP / 32, COUT / 32, BB);                 // (256, 8, 4)
    dim3 ablk(32, 8);

    transpose_p2_kernel<<<dim3(SP / 32, D2 / 32, BB), ablk>>>(points2);
    knn_kernel<<<dim3(NP / 256, BB), 256>>>(xyz1, xyz2);
    interp_kernel<<<dim3(NP / 32, BB), 256>>>();
    convert_p1_kernel<<<dim3(NP / 32, D1 / 32, BB), ablk>>>(points1);

    // fuse: 384 -> 256, BN, relu -> x (fp32) + bt (bf16 T)
    convert_w_kernel<<<(COUT * CIN + 255) / 256, 256>>>(fuse_W, COUT * CIN);
    gemm_mma_kernel<CIN><<<ggrid, 256, SMEM_GEMM>>>(fuse_b);
    finalize_kernel<<<COUT, 256>>>(fuse_g, fuse_be);
    applyT_kernel<false, true, true><<<agrid, ablk>>>(nullptr, x);

    for (int i = 0; i < 2; i++) {
        convert_w_kernel<<<(COUT * COUT + 255) / 256, 256>>>(blk_W1 + (size_t)i * COUT * COUT, COUT * COUT);
        gemm_mma_kernel<COUT><<<ggrid, 256, SMEM_GEMM>>>(blk_b1 + (size_t)i * COUT);
        finalize_kernel<<<COUT, 256>>>(blk_g1 + (size_t)i * COUT, blk_be1 + (size_t)i * COUT);
        applyT_kernel<false, false, true><<<agrid, ablk>>>(nullptr, nullptr);   // y: bt only

        convert_w_kernel<<<(COUT * COUT + 255) / 256, 256>>>(blk_W2 + (size_t)i * COUT * COUT, COUT * COUT);
        gemm_mma_kernel<COUT><<<ggrid, 256, SMEM_GEMM>>>(blk_b2 + (size_t)i * COUT);
        finalize_kernel<<<COUT, 256>>>(blk_g2 + (size_t)i * COUT, blk_be2 + (size_t)i * COUT);
        if (i == 0)
            applyT_kernel<true, true, true><<<agrid, ablk>>>(x, x);
        else
            applyT_kernel<true, true, false><<<agrid, ablk>>>(x, out);
    }
}

// round 6
// speedup vs baseline: 1.8519x; 1.0936x over previous
#include <cuda_runtime.h>
#include <cuda_bf16.h>
#include <cstdint>

#define BB   4
#define NP   8192
#define SP   2048
#define D1   128
#define D2   256
#define CIN  384
#define COUT 256
#define RS   384          // row stride (K elems) of transposed bf16 activation buffers
#define BN_EPS 1e-5f

#define BM   128
#define BN   64
#define BKc  32
#define SST  40           // smem row stride in bf16 (80 B, conflict-free for ldmatrix)
#define NSLOT 512         // (NP/BN) * BB partial-stat slots per channel

#define WTOT   (COUT * CIN + 4 * COUT * COUT)   // 360448
#define OFF_W1 (COUT * CIN)                     // 98304
#define OFF_W2 (OFF_W1 + 2 * COUT * COUT)       // 229376

// ---------------- scratch (no cudaMalloc allowed) ----------------
__device__ float g_p2t[BB * SP * D2];                    //  8 MB
__device__ float g_t  [(size_t)BB * COUT * NP];          // 33 MB raw GEMM out
__device__ __nv_bfloat16 g_bth[(size_t)BB * NP * RS];    // trunk X^T hi  [b][n][c]
__device__ __nv_bfloat16 g_btl[(size_t)BB * NP * RS];    // trunk X^T lo
__device__ __nv_bfloat16 g_byh[(size_t)BB * NP * RS];    // scratch (block intermediate y)
__device__ __nv_bfloat16 g_byl[(size_t)BB * NP * RS];
__device__ __nv_bfloat16 g_wh[WTOT];                     // all weights hi
__device__ __nv_bfloat16 g_wl[WTOT];
__device__ float g_psum[COUT * NSLOT];
__device__ float g_psq [COUT * NSLOT];
__device__ int   g_idx[BB * NP * 3];
__device__ float g_w  [BB * NP * 3];
__device__ float g_na [COUT];
__device__ float g_nb [COUT];

__device__ __forceinline__ void bf16_split(float v, __nv_bfloat16& hi, __nv_bfloat16& lo) {
    hi = __float2bfloat16(v);
    lo = __float2bfloat16(v - __bfloat162float(hi));
}
__device__ __forceinline__ uint32_t smem_u32(const void* p) {
    uint32_t a;
    asm("{ .reg .u64 t; cvta.to.shared.u64 t, %1; cvt.u32.u64 %0, t; }" : "=r"(a) : "l"(p));
    return a;
}
__device__ __forceinline__ void mma16816(float* c, const uint32_t* a, const uint32_t* b) {
    asm volatile(
        "mma.sync.aligned.m16n8k16.row.col.f32.bf16.bf16.f32 "
        "{%0,%1,%2,%3}, {%4,%5,%6,%7}, {%8,%9}, {%0,%1,%2,%3};"
        : "+f"(c[0]), "+f"(c[1]), "+f"(c[2]), "+f"(c[3])
        : "r"(a[0]), "r"(a[1]), "r"(a[2]), "r"(a[3]), "r"(b[0]), "r"(b[1]));
}
__device__ __forceinline__ void ldsm4(uint32_t* r, uint32_t addr) {
    asm volatile("ldmatrix.sync.aligned.m8n8.x4.shared.b16 {%0,%1,%2,%3}, [%4];"
        : "=r"(r[0]), "=r"(r[1]), "=r"(r[2]), "=r"(r[3]) : "r"(addr));
}
__device__ __forceinline__ void cp16(uint32_t daddr, const void* src) {
    asm volatile("cp.async.cg.shared.global [%0], [%1], 16;" :: "r"(daddr), "l"(src));
}

// ---------------- KNN (3-NN over S=2048, smem-resident) ----------------
__global__ void __launch_bounds__(128) knn_kernel(const float* __restrict__ xyz1,
                                                  const float* __restrict__ xyz2) {
    __shared__ float sx[SP], sy[SP], sz[SP], sn[SP];
    int b = blockIdx.y;
    const float* x2 = xyz2 + (size_t)b * 3 * SP;
    for (int i = threadIdx.x; i < SP; i += 128) {
        float X = x2[i], Y = x2[SP + i], Z = x2[2 * SP + i];
        sx[i] = X; sy[i] = Y; sz[i] = Z; sn[i] = X * X + Y * Y + Z * Z;
    }
    __syncthreads();
    int n = blockIdx.x * 128 + threadIdx.x;
    const float* x1 = xyz1 + (size_t)b * 3 * NP;
    float qx = x1[n], qy = x1[NP + n], qz = x1[2 * NP + n];
    float qn = qx * qx + qy * qy + qz * qz;

    float d0 = 3.4e38f, d1 = 3.4e38f, d2v = 3.4e38f;
    int i0 = 0, i1 = 0, i2 = 0;
#pragma unroll 4
    for (int s = 0; s < SP; s++) {
        float dot = qx * sx[s] + qy * sy[s] + qz * sz[s];
        float d = qn + sn[s] - 2.0f * dot;
        if (d < d2v) {
            if (d < d1) {
                d2v = d1; i2 = i1;
                if (d < d0) { d1 = d0; i1 = i0; d0 = d; i0 = s; }
                else        { d1 = d;  i1 = s; }
            } else { d2v = d; i2 = s; }
        }
    }
    float r0 = 1.0f / (d0 + 1e-8f);
    float r1 = 1.0f / (d1 + 1e-8f);
    float r2 = 1.0f / (d2v + 1e-8f);
    float inv = 1.0f / (r0 + r1 + r2);
    size_t base = ((size_t)b * NP + n) * 3;
    g_idx[base] = i0; g_idx[base + 1] = i1; g_idx[base + 2] = i2;
    g_w[base] = r0 * inv; g_w[base + 1] = r1 * inv; g_w[base + 2] = r2 * inv;
}

// ---------------- transpose points2 [b][c][s] -> [b][s][c] ----------------
__global__ void transpose_p2_kernel(const float* __restrict__ p2) {
    __shared__ float tile[32][33];
    int b = blockIdx.z;
    int s0 = blockIdx.x * 32, c0 = blockIdx.y * 32;
    int tx = threadIdx.x, ty = threadIdx.y;  // 32 x 8
#pragma unroll
    for (int j = 0; j < 32; j += 8)
        tile[ty + j][tx] = p2[((size_t)b * D2 + c0 + ty + j) * SP + s0 + tx];
    __syncthreads();
    float* dst = g_p2t + (size_t)b * SP * D2;
#pragma unroll
    for (int j = 0; j < 32; j += 8)
        dst[(size_t)(s0 + ty + j) * D2 + c0 + tx] = tile[tx][ty + j];
}

// ---------------- interp: writes trunk bt rows [n][128..383] ----------------
__global__ void __launch_bounds__(256) interp_kernel() {
    __shared__ float sw[32][3];
    __shared__ int   si[32][3];
    int b = blockIdx.y;
    int n0 = blockIdx.x * 32;
    int tid = threadIdx.x;
    if (tid < 96) {
        int q = tid / 3, k = tid % 3;
        size_t base = ((size_t)b * NP + n0 + q) * 3 + k;
        sw[q][k] = g_w[base];
        si[q][k] = g_idx[base];
    }
    __syncthreads();
    const float* f2 = g_p2t + (size_t)b * SP * D2;
    int c = tid;  // 0..255
#pragma unroll 4
    for (int q = 0; q < 32; q++) {
        float v = sw[q][0] * f2[(size_t)si[q][0] * D2 + c]
                + sw[q][1] * f2[(size_t)si[q][1] * D2 + c]
                + sw[q][2] * f2[(size_t)si[q][2] * D2 + c];
        __nv_bfloat16 hi, lo;
        bf16_split(v, hi, lo);
        size_t o = ((size_t)b * NP + n0 + q) * RS + D1 + c;
        g_bth[o] = hi;
        g_btl[o] = lo;
    }
}

// ---------------- points1 [b][c][n] -> trunk bt rows [n][0..127] ----------------
__global__ void convert_p1_kernel(const float* __restrict__ p1) {
    __shared__ float tile[32][33];
    int b = blockIdx.z;
    int n0 = blockIdx.x * 32, c0 = blockIdx.y * 32;
    int tx = threadIdx.x, ty = threadIdx.y;  // 32 x 8
#pragma unroll
    for (int j = 0; j < 32; j += 8)
        tile[ty + j][tx] = p1[((size_t)b * D1 + c0 + ty + j) * NP + n0 + tx];
    __syncthreads();
#pragma unroll
    for (int j = 0; j < 32; j += 8) {
        float v = tile[tx][ty + j];
        __nv_bfloat16 hi, lo;
        bf16_split(v, hi, lo);
        size_t o = ((size_t)b * NP + n0 + ty + j) * RS + c0 + tx;
        g_bth[o] = hi;
        g_btl[o] = lo;
    }
}

// ---------------- all weights fp32 -> bf16 hi/lo, one launch ----------------
__global__ void convert_w_all_kernel(const float* __restrict__ fw,
                                     const float* __restrict__ w1,
                                     const float* __restrict__ w2) {
    int i = blockIdx.x * 256 + threadIdx.x;
    if (i >= WTOT) return;
    float v;
    if (i < OFF_W1)      v = fw[i];
    else if (i < OFF_W2) v = w1[i - OFF_W1];
    else                 v = w2[i - OFF_W2];
    __nv_bfloat16 hi, lo;
    bf16_split(v, hi, lo);
    g_wh[i] = hi;
    g_wl[i] = lo;
}

// ---------------- mma.sync GEMM, 3-stage cp.async pipeline, 1 sync/K-tile,
// fused partial BN stats. t[b][m][n] = sum_c W[m][c]*X[b][c][n] + bias[m].
template <int K>
__global__ void __launch_bounds__(256) gemm_mma_kernel(
    const __nv_bfloat16* __restrict__ Wh, const __nv_bfloat16* __restrict__ Wl,
    const __nv_bfloat16* __restrict__ Bth, const __nv_bfloat16* __restrict__ Btl,
    const float* __restrict__ bias) {
    extern __shared__ __nv_bfloat16 sm[];
    const int ASZ = BM * SST;
    const int BSZ = BN * SST;
    const uint32_t ASZB = ASZ * 2, BSZB = BSZ * 2;
    const uint32_t STGB = 2 * ASZB + 2 * BSZB;    // 30720 B

    int tid = threadIdx.x, lane = tid & 31, wid = tid >> 5;
    int wm = wid & 3, wn = wid >> 2;
    int b = blockIdx.z;
    int n0 = blockIdx.x * BN, m0 = blockIdx.y * BM;
    int r = lane >> 2, qk = lane & 3;

    uint32_t sbase = smem_u32(sm);

    int g8 = lane >> 3, lr = lane & 7;
    uint32_t aoff[2], boff[2];
#pragma unroll
    for (int i = 0; i < 2; i++)
        aoff[i] = ((wm * 32 + i * 16 + (g8 & 1) * 8 + lr) * SST + (g8 >> 1) * 8) * 2;
#pragma unroll
    for (int p = 0; p < 2; p++)
        boff[p] = ((wn * 32 + p * 16 + (g8 >> 1) * 8 + lr) * SST + (g8 & 1) * 8) * 2;

    const __nv_bfloat16* bth_b = Bth + (size_t)b * NP * RS;
    const __nv_bfloat16* btl_b = Btl + (size_t)b * NP * RS;
    int brow = tid >> 2, bc = tid & 3;

    float acc[2][4][4];
#pragma unroll
    for (int i = 0; i < 2; i++)
#pragma unroll
        for (int j = 0; j < 4; j++)
#pragma unroll
            for (int q = 0; q < 4; q++) acc[i][j][q] = 0.f;

    const int NT = K / BKc;

    auto issue = [&](int t) {
        int kc = t * BKc;
        uint32_t st = sbase + (uint32_t)(t % 3) * STGB;
#pragma unroll
        for (int i = 0; i < 2; i++) {
            int idx = tid + i * 256;
            int row = idx >> 2, c = idx & 3;
            uint32_t d = st + (uint32_t)(row * SST + c * 8) * 2;
            cp16(d, Wh + (size_t)(m0 + row) * K + kc + c * 8);
            cp16(d + ASZB, Wl + (size_t)(m0 + row) * K + kc + c * 8);
        }
        {
            uint32_t d = st + 2 * ASZB + (uint32_t)(brow * SST + bc * 8) * 2;
            cp16(d, bth_b + (size_t)(n0 + brow) * RS + kc + bc * 8);
            cp16(d + BSZB, btl_b + (size_t)(n0 + brow) * RS + kc + bc * 8);
        }
        asm volatile("cp.async.commit_group;" ::: "memory");
    };

    issue(0);
    if (NT > 1) issue(1);

    for (int t = 0; t < NT; t++) {
        if (t + 1 < NT) {
            asm volatile("cp.async.wait_group 1;" ::: "memory");
        } else {
            asm volatile("cp.async.wait_group 0;" ::: "memory");
        }
        __syncthreads();              // single barrier per K-tile
        uint32_t st = sbase + (uint32_t)(t % 3) * STGB;
#pragma unroll
        for (int k16 = 0; k16 < BKc; k16 += 16) {
            uint32_t kb = (uint32_t)k16 * 2;
            uint32_t ah[2][4], al[2][4], bh[2][4], bl[2][4];
            ldsm4(ah[0], st + aoff[0] + kb);
            ldsm4(ah[1], st + aoff[1] + kb);
            ldsm4(al[0], st + ASZB + aoff[0] + kb);
            ldsm4(al[1], st + ASZB + aoff[1] + kb);
            ldsm4(bh[0], st + 2 * ASZB + boff[0] + kb);
            ldsm4(bh[1], st + 2 * ASZB + boff[1] + kb);
            ldsm4(bl[0], st + 2 * ASZB + BSZB + boff[0] + kb);
            ldsm4(bl[1], st + 2 * ASZB + BSZB + boff[1] + kb);
#pragma unroll
            for (int i = 0; i < 2; i++)
#pragma unroll
                for (int j = 0; j < 4; j++) {
                    const uint32_t* bhj = &bh[j >> 1][(j & 1) * 2];
                    const uint32_t* blj = &bl[j >> 1][(j & 1) * 2];
                    mma16816(acc[i][j], ah[i], bhj);
                    mma16816(acc[i][j], ah[i], blj);
                    mma16816(acc[i][j], al[i], bhj);
                }
        }
        if (t + 2 < NT) issue(t + 2);   // buffer (t+2)%3 == (t-1)%3: free after this iter's barrier
    }

    // ---- epilogue: bias add, store fp32 t, accumulate per-channel partial stats ----
    float* Yb = g_t + (size_t)b * COUT * NP;
    float ssum[4] = {0.f, 0.f, 0.f, 0.f}, ssq[4] = {0.f, 0.f, 0.f, 0.f};
#pragma unroll
    for (int i = 0; i < 2; i++) {
        int m = m0 + wm * 32 + i * 16 + r;
        float bs0 = bias[m], bs8 = bias[m + 8];
#pragma unroll
        for (int j = 0; j < 4; j++) {
            int n = n0 + wn * 32 + j * 8 + qk * 2;
            float v0 = acc[i][j][0] + bs0, v1 = acc[i][j][1] + bs0;
            float v2 = acc[i][j][2] + bs8, v3 = acc[i][j][3] + bs8;
            *(float2*)(Yb + (size_t)m * NP + n)       = make_float2(v0, v1);
            *(float2*)(Yb + (size_t)(m + 8) * NP + n) = make_float2(v2, v3);
            ssum[i * 2]     += v0 + v1;  ssq[i * 2]     += v0 * v0 + v1 * v1;
            ssum[i * 2 + 1] += v2 + v3;  ssq[i * 2 + 1] += v2 * v2 + v3 * v3;
        }
    }
#pragma unroll
    for (int o = 1; o < 4; o <<= 1) {
#pragma unroll
        for (int k = 0; k < 4; k++) {
            ssum[k] += __shfl_xor_sync(0xffffffff, ssum[k], o);
            ssq[k]  += __shfl_xor_sync(0xffffffff, ssq[k], o);
        }
    }
    float* sb = (float*)sm;       // [2][128][2]
    __syncthreads();
    if (qk == 0) {
#pragma unroll
        for (int k = 0; k < 4; k++) {
            int row = wm * 32 + (k >> 1) * 16 + (k & 1) * 8 + r;
            sb[(wn * 128 + row) * 2]     = ssum[k];
            sb[(wn * 128 + row) * 2 + 1] = ssq[k];
        }
    }
    __syncthreads();
    if (tid < 128) {
        float S = sb[tid * 2]     + sb[(128 + tid) * 2];
        float Q = sb[tid * 2 + 1] + sb[(128 + tid) * 2 + 1];
        int slot = blockIdx.x + gridDim.x * blockIdx.z;   // 0..511 fixed
        g_psum[(size_t)(m0 + tid) * NSLOT + slot] = S;
        g_psq [(size_t)(m0 + tid) * NSLOT + slot] = Q;
    }
}

// ---------------- finalize BN: deterministic reduction of 512 partials ----------
__global__ void __launch_bounds__(256) finalize_kernel(const float* __restrict__ gamma,
                                                       const float* __restrict__ beta) {
    int c = blockIdx.x, tid = threadIdx.x;
    float s = g_psum[(size_t)c * NSLOT + tid] + g_psum[(size_t)c * NSLOT + 256 + tid];
    float q = g_psq [(size_t)c * NSLOT + tid] + g_psq [(size_t)c * NSLOT + 256 + tid];
    __shared__ float rs[256], rq[256];
    rs[tid] = s; rq[tid] = q;
    __syncthreads();
    for (int o = 128; o > 0; o >>= 1) {
        if (tid < o) { rs[tid] += rs[tid + o]; rq[tid] += rq[tid + o]; }
        __syncthreads();
    }
    if (tid == 0) {
        float inv = 1.0f / (float)(BB * NP);
        float mean = rs[0] * inv;
        float var = rq[0] * inv - mean * mean;
        float a = gamma[c] * rsqrtf(var + BN_EPS);
        g_na[c] = a;
        g_nb[c] = beta[c] - mean * a;
    }
}

// ---------------- BN-apply: optional residual (from trunk bt), bf16 dest, fp32 out
template <bool RES, bool WOUT, bool WBT>
__global__ void applyT_kernel(const __nv_bfloat16* __restrict__ Th,
                              const __nv_bfloat16* __restrict__ Tl,
                              __nv_bfloat16* __restrict__ Dh,
                              __nv_bfloat16* __restrict__ Dl,
                              float* __restrict__ O) {
    __shared__ float ts[32][33];
    __shared__ float t2[32][33];
    int b = blockIdx.z;
    int n0 = blockIdx.x * 32, c0 = blockIdx.y * 32;
    int tx = threadIdx.x, ty = threadIdx.y;  // 32 x 8
    // phase 1: BN in [c][n] (coalesced g_t read)
#pragma unroll
    for (int j = 0; j < 32; j += 8) {
        int c = c0 + ty + j;
        size_t off = ((size_t)b * COUT + c) * NP + n0 + tx;
        ts[ty + j][tx] = fmaf(g_na[c], g_t[off], g_nb[c]);
    }
    __syncthreads();
    // phase 2: [n][c] domain — residual add, relu, bt write
#pragma unroll
    for (int j = 0; j < 32; j += 8) {
        int n = n0 + ty + j, c = c0 + tx;
        float v = ts[tx][ty + j];
        size_t o = ((size_t)b * NP + n) * RS + c;
        if (RES)
            v += __bfloat162float(Th[o]) + __bfloat162float(Tl[o]);
        v = fmaxf(v, 0.f);
        if (WBT) {
            __nv_bfloat16 hi, lo;
            bf16_split(v, hi, lo);
            Dh[o] = hi;
            Dl[o] = lo;
        }
        if (WOUT) t2[tx][ty + j] = v;
    }
    if (WOUT) {
        __syncthreads();
#pragma unroll
        for (int j = 0; j < 32; j += 8)
            O[((size_t)b * COUT + c0 + ty + j) * NP + n0 + tx] = t2[ty + j][tx];
    }
}

// ---------------- launch ----------------
extern "C" void kernel_launch(void* const* d_in, const int* in_sizes, int n_in,
                              void* d_out, int out_size) {
    const float* xyz1    = (const float*)d_in[0];
    const float* xyz2    = (const float*)d_in[1];
    const float* points1 = (const float*)d_in[2];
    const float* points2 = (const float*)d_in[3];
    const float* fuse_W  = (const float*)d_in[4];
    const float* fuse_b  = (const float*)d_in[5];
    const float* fuse_g  = (const float*)d_in[6];
    const float* fuse_be = (const float*)d_in[7];
    const float* blk_W1  = (const float*)d_in[8];
    const float* blk_b1  = (const float*)d_in[9];
    const float* blk_g1  = (const float*)d_in[10];
    const float* blk_be1 = (const float*)d_in[11];
    const float* blk_W2  = (const float*)d_in[12];
    const float* blk_b2  = (const float*)d_in[13];
    const float* blk_g2  = (const float*)d_in[14];
    const float* blk_be2 = (const float*)d_in[15];
    float* out = (float*)d_out;

    void* pv;
    cudaGetSymbolAddress(&pv, g_wh);  __nv_bfloat16* wh = (__nv_bfloat16*)pv;
    cudaGetSymbolAddress(&pv, g_wl);  __nv_bfloat16* wl = (__nv_bfloat16*)pv;
    cudaGetSymbolAddress(&pv, g_bth); __nv_bfloat16* th = (__nv_bfloat16*)pv;
    cudaGetSymbolAddress(&pv, g_btl); __nv_bfloat16* tl = (__nv_bfloat16*)pv;
    cudaGetSymbolAddress(&pv, g_byh); __nv_bfloat16* yh = (__nv_bfloat16*)pv;
    cudaGetSymbolAddress(&pv, g_byl); __nv_bfloat16* yl = (__nv_bfloat16*)pv;

    const int SMEM_GEMM = 3 * (2 * BM * SST + 2 * BN * SST) * 2;  // 92160 B
    cudaFuncSetAttribute(gemm_mma_kernel<CIN>,  cudaFuncAttributeMaxDynamicSharedMemorySize, SMEM_GEMM);
    cudaFuncSetAttribute(gemm_mma_kernel<COUT>, cudaFuncAttributeMaxDynamicSharedMemorySize, SMEM_GEMM);

    dim3 ggrid(NP / BN, COUT / BM, BB);                 // (128, 2, 4)
    dim3 agrid(NP / 32, COUT / 32, BB);                 // (256, 8, 4)
    dim3 ablk(32, 8);

    convert_w_all_kernel<<<(WTOT + 255) / 256, 256>>>(fuse_W, blk_W1, blk_W2);
    transpose_p2_kernel<<<dim3(SP / 32, D2 / 32, BB), ablk>>>(points2);
    knn_kernel<<<dim3(NP / 128, BB), 128>>>(xyz1, xyz2);
    interp_kernel<<<dim3(NP / 32, BB), 256>>>();
    convert_p1_kernel<<<dim3(NP / 32, D1 / 32, BB), ablk>>>(points1);

    // fuse: 384 -> 256, BN, relu -> trunk bt
    gemm_mma_kernel<CIN><<<ggrid, 256, SMEM_GEMM>>>(wh, wl, th, tl, fuse_b);
    finalize_kernel<<<COUT, 256>>>(fuse_g, fuse_be);
    applyT_kernel<false, false, true><<<agrid, ablk>>>(nullptr, nullptr, th, tl, nullptr);

    for (int i = 0; i < 2; i++) {
        gemm_mma_kernel<COUT><<<ggrid, 256, SMEM_GEMM>>>(
            wh + OFF_W1 + (size_t)i * COUT * COUT, wl + OFF_W1 + (size_t)i * COUT * COUT,
            th, tl, blk_b1 + (size_t)i * COUT);
        finalize_kernel<<<COUT, 256>>>(blk_g1 + (size_t)i * COUT, blk_be1 + (size_t)i * COUT);
        applyT_kernel<false, false, true><<<agrid, ablk>>>(nullptr, nullptr, yh, yl, nullptr);

        gemm_mma_kernel<COUT><<<ggrid, 256, SMEM_GEMM>>>(
            wh + OFF_W2 + (size_t)i * COUT * COUT, wl + OFF_W2 + (size_t)i * COUT * COUT,
            yh, yl, blk_b2 + (size_t)i * COUT);
        finalize_kernel<<<COUT, 256>>>(blk_g2 + (size_t)i * COUT, blk_be2 + (size_t)i * COUT);
        if (i == 0)
            applyT_kernel<true, false, true><<<agrid, ablk>>>(th, tl, th, tl, nullptr);
        else
            applyT_kernel<true, true, false><<<agrid, ablk>>>(th, tl, nullptr, nullptr, out);
    }
}